// round 10
// baseline (speedup 1.0000x reference)
#include <cuda_runtime.h>

// Problem constants (fixed shapes from setup_inputs)
#define BB 32
#define HH 480
#define WW 640
#define HWsz (HH*WW)          // 307200
#define CIM 3
#define OHh 34
#define OWw 45
#define NR 1530               // OHh*OWw
#define KTOP 153
#define RESH 14
#define PHLF 12
#define PSZ 625
#define EPSf 1e-5f
#define MIN_SAMP 4
#define NBG 30
#define CHUNK (HWsz/NBG)      // 10240
#define NBG2 60
#define CHUNK2 (HWsz/NBG2)    // 5120
#define RWORDS 20             // words per image row (640/32)
#define IWORDS (HWsz/32)      // 9600 words per image
#define PGRID (BB*KTOP)       // 4896
#define HGRID (NBG*BB)        // 960 hist blocks
#define EGRID (BB*NR*4/256)   // 765 edge blocks
#define GGRID (BB*NBG2)       // 1920 gather blocks

// ----------------------------- scratch (zero-init; zero-on-consume) --------
__device__ unsigned d_mbits[BB*HWsz/32];
__device__ unsigned d_vbits[BB*HWsz/32];
__device__ float    d_resized[BB*NR];
__device__ int      d_coords[BB*KTOP*2];
__device__ float    d_ep[BB*KTOP];
__device__ int      d_validp[BB*KTOP];
__device__ unsigned d_hist1[BB*2*2048];       // zeroed by select1 after read
__device__ unsigned d_ncnt[BB];               // zeroed by k_final
__device__ unsigned d_sel1[BB*2];
__device__ unsigned d_cb1[BB*2];
__device__ float    d_med[BB*2];
__device__ float    d_scale[BB*2];
__device__ float    d_vsum[BB*2];             // zeroed by selectC
__device__ float    d_slo[BB*2];              // zeroed by selectC
__device__ float    d_gsum[BB];               // zeroed by k_final
__device__ unsigned d_ccnt[BB*2];             // zeroed by selectC
__device__ float    d_cand[(size_t)BB*2*HWsz];

// ----------------------------- helpers -------------------------------------
__device__ __forceinline__ unsigned keyf(float v){
    unsigned b=__float_as_uint(v);
    return b ^ ((b & 0x80000000u) ? 0xFFFFFFFFu : 0x80000000u);
}
__device__ __forceinline__ float unkey(unsigned k){
    unsigned b = (k & 0x80000000u) ? (k ^ 0x80000000u) : ~k;
    return __uint_as_float(b);
}
__device__ __forceinline__ float bsum256(float v, float* red, int t){
    red[t]=v; __syncthreads();
    #pragma unroll
    for(int s=128;s>0;s>>=1){ if(t<s) red[t]+=red[t+s]; __syncthreads(); }
    float r=red[0]; __syncthreads();
    return r;
}
// warp shfl full-reduce
__device__ __forceinline__ float wsumf(float v){
    #pragma unroll
    for(int o=16;o>0;o>>=1) v+=__shfl_xor_sync(0xffffffffu,v,o);
    return v;
}
// cheap per-warp mask dtype probe: 0=u8, 1=int32(0/1), 2=float32(0/1.0f)
__device__ __forceinline__ int detect_mode(const unsigned* m){
    unsigned lane=threadIdx.x&31;
    unsigned v0=m[lane], v1=m[lane+32];
    bool allb=__all_sync(0xffffffffu,(v0<=1u)&&(v1<=1u));
    bool allf=__all_sync(0xffffffffu,(v0==0u||v0==0x3F800000u)&&(v1==0u||v1==0x3F800000u));
    return allb?1:(allf?2:0);
}
// warp-aggregated histogram increment; only used in compile-time-uniform loops.
__device__ __forceinline__ void aggInc(unsigned* h, unsigned bn){
    unsigned mm=__match_any_sync(0xffffffffu,bn);
    if(bn!=0xFFFFFFFFu){
        int leader=__ffs(mm)-1;
        if((int)(threadIdx.x&31)==leader) atomicAdd(&h[bn],(unsigned)__popc(mm));
    }
}

// single radix select (topk): rank kk ascending among valid keys (exact, 32-bit)
template<int NOWN>
__device__ __forceinline__ unsigned radix_sel(const unsigned (&key)[NOWN],
                                              const bool (&vl)[NOWN],
                                              unsigned kk,
                                              unsigned* hist, unsigned* wsum,
                                              unsigned* shb){
    int t=threadIdx.x, lane=t&31, wid=t>>5;
    unsigned prefix=0u;
    #pragma unroll
    for(int lvl=0;lvl<4;lvl++){
        const int sh=24-8*lvl;
        hist[t]=0u; __syncthreads();
        #pragma unroll
        for(int r=0;r<NOWN;r++){
            unsigned bn=0xFFFFFFFFu;
            if(vl[r]){
                unsigned k=key[r];
                bool ok=(lvl==0)||((k>>(sh+8))==prefix);
                if(ok) bn=(k>>sh)&255u;
            }
            aggInc(hist,bn);
        }
        __syncthreads();
        unsigned c=hist[t], x=c;
        #pragma unroll
        for(int o=1;o<32;o<<=1){ unsigned v=__shfl_up_sync(0xffffffffu,x,o); if(lane>=o)x+=v; }
        if(lane==31) wsum[wid]=x;
        __syncthreads();
        if(t==0){ unsigned s=0; for(int i=0;i<8;i++){ s+=wsum[i]; wsum[i]=s; } }
        __syncthreads();
        unsigned incl = x + (wid? wsum[wid-1]:0u);
        unsigned excl = incl - c;
        if(excl<=kk && kk<incl){ shb[0]=(unsigned)t; shb[1]=excl; }
        __syncthreads();
        prefix=(prefix<<8)|shb[0];
        kk-=shb[1];
        __syncthreads();
    }
    return prefix;
}

// ----------------------------- pack validity mask ----------------------------
__global__ __launch_bounds__(256) void k_packvm(const void* __restrict__ vm){
    int f=blockIdx.x*256+threadIdx.x;
    int mode=detect_mode((const unsigned*)vm);
    bool m0,m1,m2,m3;
    if(mode!=0){
        uint4 v=((const uint4*)vm)[f];
        m0=v.x!=0u; m1=v.y!=0u; m2=v.z!=0u; m3=v.w!=0u;
    } else {
        uchar4 v=((const uchar4*)vm)[f];
        m0=v.x; m1=v.y; m2=v.z; m3=v.w;
    }
    unsigned nib=(m0?1u:0u)|(m1?2u:0u)|(m2?4u:0u)|(m3?8u:0u);
    unsigned w=nib<<(4*(threadIdx.x&7));
    w|=__shfl_xor_sync(0xffffffffu,w,1);
    w|=__shfl_xor_sync(0xffffffffu,w,2);
    w|=__shfl_xor_sync(0xffffffffu,w,4);
    if((threadIdx.x&7)==0) d_vbits[f>>3]=w;
}

// ----------------------------- edge body -------------------------------------
__device__ __forceinline__ float edge_at(const float* __restrict__ img, int b, int y, int x){
    if(y<3 || y>HH-4 || x<3 || x>WW-4) return 0.f;
    int rb=b*IWORDS;
    int q=(x-1)>>5, s=(x-1)&31;
    unsigned a0=d_vbits[rb+(y-1)*RWORDS+q]&d_vbits[rb+y*RWORDS+q]&d_vbits[rb+(y+1)*RWORDS+q];
    unsigned bits;
    if(s<=29) bits=(a0>>s)&7u;
    else{
        unsigned a1=d_vbits[rb+(y-1)*RWORDS+q+1]&d_vbits[rb+y*RWORDS+q+1]&d_vbits[rb+(y+1)*RWORDS+q+1];
        bits=((a0>>s)|(a1<<(32-s)))&7u;
    }
    if(bits!=7u) return 0.f;
    float gx2=0.f, gy2=0.f;
    #pragma unroll
    for(int c=0;c<CIM;c++){
        const float* p = img + (size_t)(b*CIM+c)*HWsz;
        float v00=__ldg(&p[(y-1)*WW+x-1]), v01=__ldg(&p[(y-1)*WW+x]), v02=__ldg(&p[(y-1)*WW+x+1]);
        float v10=__ldg(&p[(y  )*WW+x-1]),                            v12=__ldg(&p[(y  )*WW+x+1]);
        float v20=__ldg(&p[(y+1)*WW+x-1]), v21=__ldg(&p[(y+1)*WW+x]), v22=__ldg(&p[(y+1)*WW+x+1]);
        float sx=((v02+2.f*v12+v22)-(v00+2.f*v10+v20))*0.125f;
        float sy=((v20+2.f*v21+v22)-(v00+2.f*v01+v02))*0.125f;
        gx2+=sx*sx; gy2+=sy*sy;
    }
    return sqrtf((gx2+gy2)*(1.f/3.f));
}

__device__ void edge_body(const float* __restrict__ img, int ebx){
    int gid=ebx*256+threadIdx.x;
    int id=gid>>2, corner=gid&3;
    int b=id/NR, o=id%NR, oy=o/OWw, ox=o%OWw;
    const float ry=(float)(480.0/34.0), rx=(float)(640.0/45.0);
    float cy=fminf(fmaxf((oy+0.5f)*ry-0.5f,0.f),(float)(HH-1));
    float cx=fminf(fmaxf((ox+0.5f)*rx-0.5f,0.f),(float)(WW-1));
    int y0=(int)floorf(cy), x0=(int)floorf(cx);
    int y1=min(y0+1,HH-1),  x1=min(x0+1,WW-1);
    float wy=cy-(float)y0,  wx=cx-(float)x0;
    int y=(corner&2)? y1:y0;
    int x=(corner&1)? x1:x0;
    float w=((corner&2)? wy:(1.f-wy))*((corner&1)? wx:(1.f-wx));
    float e=edge_at(img,b,y,x)*w;
    e+=__shfl_xor_sync(0xffffffffu,e,1);
    e+=__shfl_xor_sync(0xffffffffu,e,2);
    if(corner==0) d_resized[id]=e;
}

// ----------------------------- hist body (pack mk + level-1 histogram) -------
__device__ void hist_body(const float* __restrict__ in, const float* __restrict__ tg,
                          const void* __restrict__ mk, int b, int cx,
                          unsigned* h, float* facc){
    int t=threadIdx.x, lane=t&31;
    for(int i=t;i<4096;i+=256) h[i]=0u;
    if(t==0){ facc[0]=0.f; facc[1]=0.f; facc[2]=0.f; }
    int mode=detect_mode((const unsigned*)mk);
    __syncthreads();
    int fbase=(b*HWsz+cx*CHUNK)>>2;
    float sI=0.f,sT=0.f,nloc=0.f;
    #pragma unroll 2
    for(int j=0;j<CHUNK/1024;j++){
        int f=fbase+j*256+t;
        bool m[4];
        if(mode!=0){
            uint4 v=((const uint4*)mk)[f];
            m[0]=v.x!=0u; m[1]=v.y!=0u; m[2]=v.z!=0u; m[3]=v.w!=0u;
        } else {
            uchar4 v=((const uchar4*)mk)[f];
            m[0]=v.x; m[1]=v.y; m[2]=v.z; m[3]=v.w;
        }
        unsigned nib=(m[0]?1u:0u)|(m[1]?2u:0u)|(m[2]?4u:0u)|(m[3]?8u:0u);
        unsigned wv=nib<<(4*(t&7));
        wv|=__shfl_xor_sync(0xffffffffu,wv,1);
        wv|=__shfl_xor_sync(0xffffffffu,wv,2);
        wv|=__shfl_xor_sync(0xffffffffu,wv,4);
        if((t&7)==0) d_mbits[f>>3]=wv;
        float4 vi=((const float4*)in)[f];
        float4 vt=((const float4*)tg)[f];
        float ei[4]={vi.x,vi.y,vi.z,vi.w};
        float et[4]={vt.x,vt.y,vt.z,vt.w};
        #pragma unroll
        for(int e=0;e<4;e++){
            if(m[e]){
                atomicAdd(&h[keyf(ei[e])>>21],1u);
                atomicAdd(&h[2048u+(keyf(et[e])>>21)],1u);
                nloc+=1.f; sI+=ei[e]; sT+=et[e];
            }
        }
    }
    nloc=wsumf(nloc); sI=wsumf(sI); sT=wsumf(sT);
    if(lane==0){
        atomicAdd(&facc[0],nloc);
        atomicAdd(&facc[1],sI);
        atomicAdd(&facc[2],sT);
    }
    __syncthreads();
    for(int i=t;i<4096;i+=256){
        unsigned v=h[i];
        if(v) atomicAdd(&d_hist1[b*4096+i],v);
    }
    if(t==0){
        atomicAdd(&d_ncnt[b],(unsigned)(facc[0]+0.5f));
        atomicAdd(&d_vsum[b*2+0],facc[1]);
        atomicAdd(&d_vsum[b*2+1],facc[2]);
    }
}

// merged launch: hist blocks + edge blocks (independent, co-scheduled)
__global__ __launch_bounds__(256) void k_hist_edge(const float* __restrict__ in,
                                                   const float* __restrict__ tg,
                                                   const void* __restrict__ mk,
                                                   const float* __restrict__ img){
    __shared__ unsigned h[4096];
    __shared__ float facc[4];
    int bx=blockIdx.x;
    if(bx<HGRID) hist_body(in,tg,mk,bx%BB,bx/BB,h,facc);
    else         edge_body(img,bx-HGRID);
}

// ----------------------------- merged top-k + level-1 select -----------------
__device__ void topk_body(unsigned* hist, unsigned* wsum, unsigned* shb,
                          int* ties, int* cnts){
    int b=blockIdx.x, t=threadIdx.x;
    unsigned key[6]; bool vl[6];
    #pragma unroll
    for(int r=0;r<6;r++){
        int i=t+256*r;
        vl[r]=(i<NR);
        key[r]= vl[r] ? keyf(d_resized[b*NR+i]) : 0u;
    }
    if(t==0){ cnts[0]=0; cnts[1]=0; }
    __syncthreads();
    unsigned T=radix_sel<6>(key,vl,(unsigned)(NR-KTOP),hist,wsum,shb);
    #pragma unroll
    for(int r=0;r<6;r++) if(vl[r]){
        int i=t+256*r;
        if(key[r]>T){
            int s=atomicAdd(&cnts[0],1);
            d_coords[(b*KTOP+s)*2+0]=(i/OWw)*RESH;
            d_coords[(b*KTOP+s)*2+1]=(i%OWw)*RESH;
        } else if(key[r]==T){
            int s=atomicAdd(&cnts[1],1);
            ties[s]=i;
        }
    }
    __syncthreads();
    int r_need=KTOP-cnts[0];
    int nt=cnts[1];
    for(int j=t;j<nt;j+=256){
        int idx=ties[j]; int rk=0;
        for(int q=0;q<nt;q++) rk+=(ties[q]<idx);
        if(rk<r_need){
            int s=cnts[0]+rk;
            d_coords[(b*KTOP+s)*2+0]=(idx/OWw)*RESH;
            d_coords[(b*KTOP+s)*2+1]=(idx%OWw)*RESH;
        }
    }
}
// stages d_hist1 into smem, zeroing the global copy for the next run
__device__ void select1_body(int bt, unsigned* stage, unsigned* part){
    int t=threadIdx.x;
    unsigned* gh=&d_hist1[(bt>>1)*4096+(bt&1)*2048];
    unsigned loc=0;
    #pragma unroll
    for(int i=0;i<8;i++){
        unsigned v=gh[t*8+i];
        gh[t*8+i]=0u;
        stage[t*8+i]=v;
        loc+=v;
    }
    part[t]=loc; __syncthreads();
    if(t!=0) return;
    unsigned n=d_ncnt[bt>>1];
    if(n==0){ d_sel1[bt]=0xFFFFFFFFu; d_cb1[bt]=0u; return; }
    unsigned kk=(n-1u)>>1;
    unsigned cum=0; int c=0;
    while(c<256 && cum+part[c]<=kk){ cum+=part[c]; c++; }
    int bin=c*8;
    while(cum+stage[bin]<=kk){ cum+=stage[bin]; bin++; }
    d_sel1[bt]=(unsigned)bin; d_cb1[bt]=cum;
}
__global__ __launch_bounds__(256) void k_topk_sel(){
    __shared__ unsigned sh[2304];
    __shared__ int cnts[2];
    if(blockIdx.x<BB)
        topk_body(sh,sh+256,sh+264,(int*)(sh+272),cnts);
    else
        select1_body(blockIdx.x-BB,sh,sh+2048);
}

// ----------------------------- gather body (block-staged compaction) ---------
__device__ void gather_body(const float* __restrict__ in, const float* __restrict__ tg,
                            int b, int cx, unsigned* sh, float* facc){
    unsigned (*sbal0)[4]=(unsigned(*)[4])(sh);
    unsigned (*sbal1)[4]=(unsigned(*)[4])(sh+32);
    unsigned (*woff0)[4]=(unsigned(*)[4])(sh+64);
    unsigned (*woff1)[4]=(unsigned(*)[4])(sh+96);
    int t=threadIdx.x, lane=t&31, wid=t>>5;
    if(t==0){ facc[0]=0.f; facc[1]=0.f; }
    unsigned s0=d_sel1[b*2+0], s1=d_sel1[b*2+1];
    int fbase=(b*HWsz+cx*CHUNK2)>>2;
    float lo0=0.f, lo1=0.f;
    float* c0=&d_cand[(size_t)(b*2+0)*HWsz];
    float* c1=&d_cand[(size_t)(b*2+1)*HWsz];
    unsigned lmask=(1u<<lane)-1u;
    for(int j=0;j<CHUNK2/1024;j++){
        int f=fbase+j*256+t;
        unsigned mb=(d_mbits[f>>3]>>((f&7)*4))&0xFu;
        float4 vi=((const float4*)in)[f];
        float4 vt=((const float4*)tg)[f];
        float ei[4]={vi.x,vi.y,vi.z,vi.w};
        float et[4]={vt.x,vt.y,vt.z,vt.w};
        bool p0[4],p1[4];
        #pragma unroll
        for(int e=0;e<4;e++){
            bool a=(mb>>e)&1u;
            unsigned ki=a? keyf(ei[e]):0u;
            unsigned pi=ki>>21;
            p0[e]=a&&(pi==s0);
            if(a&&pi<s0) lo0+=ei[e];
            unsigned kt=a? keyf(et[e]):0u;
            unsigned pt=kt>>21;
            p1[e]=a&&(pt==s1);
            if(a&&pt<s1) lo1+=et[e];
        }
        #pragma unroll
        for(int e=0;e<4;e++){
            unsigned b0=__ballot_sync(0xffffffffu,p0[e]);
            unsigned b1=__ballot_sync(0xffffffffu,p1[e]);
            if(lane==0){ sbal0[wid][e]=b0; sbal1[wid][e]=b1; }
        }
        __syncthreads();
        if(t==0){
            unsigned run=0;
            #pragma unroll
            for(int w=0;w<8;w++)
                #pragma unroll
                for(int e=0;e<4;e++){ woff0[w][e]=run; run+=__popc(sbal0[w][e]); }
            unsigned base=run? atomicAdd(&d_ccnt[b*2+0],run):0u;
            #pragma unroll
            for(int w=0;w<8;w++)
                #pragma unroll
                for(int e=0;e<4;e++) woff0[w][e]+=base;
        } else if(t==32){
            unsigned run=0;
            #pragma unroll
            for(int w=0;w<8;w++)
                #pragma unroll
                for(int e=0;e<4;e++){ woff1[w][e]=run; run+=__popc(sbal1[w][e]); }
            unsigned base=run? atomicAdd(&d_ccnt[b*2+1],run):0u;
            #pragma unroll
            for(int w=0;w<8;w++)
                #pragma unroll
                for(int e=0;e<4;e++) woff1[w][e]+=base;
        }
        __syncthreads();
        #pragma unroll
        for(int e=0;e<4;e++){
            if(p0[e]) c0[woff0[wid][e]+__popc(sbal0[wid][e]&lmask)]=ei[e];
            if(p1[e]) c1[woff1[wid][e]+__popc(sbal1[wid][e]&lmask)]=et[e];
        }
        __syncthreads();
    }
    lo0=wsumf(lo0); lo1=wsumf(lo1);
    if(lane==0){ atomicAdd(&facc[0],lo0); atomicAdd(&facc[1],lo1); }
    __syncthreads();
    if(t==0){
        atomicAdd(&d_slo[b*2+0],lo0>=0.f?facc[0]:facc[0]);
        atomicAdd(&d_slo[b*2+1],facc[1]);
    }
}

// ----------------------------- patch body: dual 3x8-bit select on top-24 bits
__device__ void patch_body(const float* __restrict__ in, const float* __restrict__ tg,
                           int blk, unsigned* h /*512*/, unsigned* waux /*16*/,
                           unsigned* shb /*5*/, float* facc /*3*/){
    int b=blk/KTOP, p=blk%KTOP, t=threadIdx.x, lane=t&31, wid=t>>5;
    int cy=d_coords[(b*KTOP+p)*2+0], cx=d_coords[(b*KTOP+p)*2+1];
    unsigned ka[3],kb[3]; float va[3],vb[3]; bool vl[3];
    int nown=2+(t<113);
    #pragma unroll
    for(int r=0;r<3;r++){
        vl[r]=false; ka[r]=0u; kb[r]=0u; va[r]=0.f; vb[r]=0.f;
        if(r<nown){
            int i=t+256*r;
            int y=cy+i/25-PHLF, x=cx+i%25-PHLF;
            bool inb=(y>=0)&&(y<HH)&&(x>=0)&&(x<WW);
            if(inb){
                int gi=b*HWsz+y*WW+x;
                bool m=(d_mbits[gi>>5]>>(gi&31))&1u;
                if(m){
                    vl[r]=true;
                    va[r]=in[gi]; vb[r]=tg[gi];
                    ka[r]=keyf(va[r])>>8;   // top-24 bits only
                    kb[r]=keyf(vb[r])>>8;
                }
            }
        }
    }
    if(t==0){ facc[0]=0.f; facc[1]=0.f; facc[2]=0.f; }
    // dual 3-level (8 bits each) select over 24-bit keys; n from level-0 scan
    unsigned pa=0u, pb=0u, kka=0u, kkb=0u, n=0u;
    #pragma unroll
    for(int lvl=0;lvl<3;lvl++){
        const int SHF=16-8*lvl;
        h[t]=0u; h[256+t]=0u;
        if(t==0){ shb[0]=0u; shb[1]=0u; shb[2]=0u; shb[3]=0u; }
        __syncthreads();
        if(lvl==0){
            // concentrated bins -> warp-aggregated
            #pragma unroll
            for(int r=0;r<3;r++){
                unsigned bnA=vl[r]? ((ka[r]>>SHF)&255u):0xFFFFFFFFu;
                unsigned bnB=vl[r]? (256u+((kb[r]>>SHF)&255u)):0xFFFFFFFFu;
                aggInc(h,bnA);
                aggInc(h,bnB);
            }
        } else {
            // spread bins -> plain atomics (no collectives)
            #pragma unroll
            for(int r=0;r<3;r++) if(vl[r]){
                if((ka[r]>>(SHF+8))==pa) atomicAdd(&h[(ka[r]>>SHF)&255u],1u);
                if((kb[r]>>(SHF+8))==pb) atomicAdd(&h[256u+((kb[r]>>SHF)&255u)],1u);
            }
        }
        __syncthreads();
        unsigned cA=h[t], cB=h[256+t], xA=cA, xB=cB;
        #pragma unroll
        for(int o=1;o<32;o<<=1){
            unsigned vA=__shfl_up_sync(0xffffffffu,xA,o);
            unsigned vB=__shfl_up_sync(0xffffffffu,xB,o);
            if(lane>=o){ xA+=vA; xB+=vB; }
        }
        if(lane==31){ waux[wid]=xA; waux[8+wid]=xB; }
        __syncthreads();
        if(t==0){
            unsigned s=0; for(int i=0;i<8;i++){ s+=waux[i]; waux[i]=s; }
            if(lvl==0) shb[4]=s;                   // n = level-0 A total
            s=0; for(int i=8;i<16;i++){ s+=waux[i]; waux[i]=s; }
        }
        __syncthreads();
        if(lvl==0){
            n=shb[4];
            kka=kkb=(n>0u)?((n-1u)>>1):0u;
        }
        unsigned inclA=xA+(wid?waux[wid-1]:0u), exclA=inclA-cA;
        unsigned inclB=xB+(wid?waux[8+wid-1]:0u), exclB=inclB-cB;
        if(exclA<=kka && kka<inclA){ shb[0]=(unsigned)t; shb[1]=exclA; }
        if(exclB<=kkb && kkb<inclB){ shb[2]=(unsigned)t; shb[3]=exclB; }
        __syncthreads();
        pa=(pa<<8)|shb[0]; kka-=shb[1];
        pb=(pb<<8)|shb[2]; kkb-=shb[3];
        __syncthreads();
    }
    // median ~= mid of selected 256-wide key bucket (<=2^-15 rel quantization)
    float medA=(n>0u)?unkey((pa<<8)|0x80u):0.f;
    float medB=(n>0u)?unkey((pb<<8)|0x80u):0.f;
    float s0=0.f,s1=0.f;
    #pragma unroll
    for(int r=0;r<3;r++) if(vl[r]){ s0+=fabsf(va[r]-medA); s1+=fabsf(vb[r]-medB); }
    s0=wsumf(s0); s1=wsumf(s1);
    if(lane==0){ atomicAdd(&facc[0],s0); atomicAdd(&facc[1],s1); }
    __syncthreads();
    float nf=fmaxf((float)n,1.f);
    float rA=1.f/fmaxf(facc[0]/nf,EPSf), rB=1.f/fmaxf(facc[1]/nf,EPSf);
    float es=0.f;
    #pragma unroll
    for(int r=0;r<3;r++) if(vl[r]){
        float a=(va[r]-medA)*rA, c=(vb[r]-medB)*rB;
        es+=fmaxf(fabsf(a-c),EPSf);
    }
    es=wsumf(es);
    if(lane==0) atomicAdd(&facc[2],es);
    __syncthreads();
    if(t==0){
        d_ep[blk]=sqrtf(fmaxf(facc[2]/nf,EPSf));
        d_validp[blk]=(n>=MIN_SAMP);
    }
}

// merged launch: gather (BW-bound) + patch (compute-bound), co-scheduled
__global__ __launch_bounds__(256) void k_gather_patch(const float* __restrict__ in,
                                                      const float* __restrict__ tg){
    __shared__ unsigned h[512];
    __shared__ unsigned waux[16];
    __shared__ unsigned shb[5];
    __shared__ float facc[3];
    int bx=blockIdx.x;
    if(bx<GGRID) gather_body(in,tg,bx%BB,bx/BB,h,facc);
    else         patch_body(in,tg,bx-GGRID,h,waux,shb,facc);
}

// ----------------------------- candidate select: exact median + scale --------
__global__ __launch_bounds__(256) void k_selectC(){
    __shared__ unsigned h[256];
    __shared__ unsigned wsum[8];
    __shared__ unsigned shb[2];
    __shared__ float rf[256];
    int bt=blockIdx.x; int b=bt>>1, t=threadIdx.x, lane=t&31, wid=t>>5;
    unsigned n=d_ncnt[b];
    unsigned sel1=d_sel1[bt];
    unsigned nc=d_ccnt[bt];
    unsigned cb1=d_cb1[bt];
    float vsum=0.f, slo0=0.f;
    if(t==0){ vsum=d_vsum[bt]; slo0=d_slo[bt]; }
    __syncthreads();
    if(t==0){ d_ccnt[bt]=0u; d_vsum[bt]=0.f; d_slo[bt]=0.f; }   // zero-on-consume
    if(n==0u || sel1==0xFFFFFFFFu){
        if(t==0){ d_med[bt]=0.f; d_scale[bt]=0.f; }
        return;
    }
    unsigned kk=((n-1u)>>1)-cb1;
    const float* cd=&d_cand[(size_t)bt*HWsz];
    unsigned pre=0u;
    const int SH[3]={13,5,0};
    const int BWD[3]={8,8,5};
    #pragma unroll
    for(int lvl=0;lvl<3;lvl++){
        int sh=SH[lvl];
        h[t]=0u; __syncthreads();
        for(unsigned i=t;i<nc;i+=256){
            unsigned k=keyf(cd[i])&0x1FFFFFu;
            if(lvl==0 || (k>>(sh+BWD[lvl]))==pre)
                atomicAdd(&h[(k>>sh)&((1u<<BWD[lvl])-1u)],1u);
        }
        __syncthreads();
        unsigned c=h[t], x=c;
        #pragma unroll
        for(int o=1;o<32;o<<=1){ unsigned v=__shfl_up_sync(0xffffffffu,x,o); if(lane>=o)x+=v; }
        if(lane==31) wsum[wid]=x;
        __syncthreads();
        if(t==0){ unsigned s=0; for(int i=0;i<8;i++){ s+=wsum[i]; wsum[i]=s; } }
        __syncthreads();
        unsigned incl=x+(wid?wsum[wid-1]:0u), excl=incl-c;
        if(excl<=kk && kk<incl){ shb[0]=(unsigned)t; shb[1]=excl; }
        __syncthreads();
        pre=(pre<<BWD[lvl])|shb[0];
        kk-=shb[1];
        __syncthreads();
    }
    unsigned medkey=(sel1<<21)|pre;
    float med=unkey(medkey);
    float sl=0.f, cl=0.f, ce=0.f;
    for(unsigned i=t;i<nc;i+=256){
        float v=cd[i];
        unsigned k=keyf(v);
        if(k<medkey){ sl+=v; cl+=1.f; }
        else if(k==medkey) ce+=1.f;
    }
    sl=bsum256(sl,rf,t);
    cl=bsum256(cl,rf,t);
    ce=bsum256(ce,rf,t);
    if(t==0){
        float C_lo=(float)cb1+cl;
        float S_lo=slo0+sl;
        float C_hi=(float)n-C_lo-ce;
        float S_hi=vsum-S_lo-ce*med;
        float sumabs=(S_hi-C_hi*med)+(C_lo*med-S_lo);
        d_med[bt]=med;
        d_scale[bt]=sumabs/fmaxf((float)n,1.f);
    }
}

// ----------------------------- global error pass -----------------------------
__global__ __launch_bounds__(256) void k_gerr(const float* __restrict__ in,
                                              const float* __restrict__ tg){
    __shared__ float facc[1];
    int b=blockIdx.y, t=threadIdx.x, lane=t&31;
    if(t==0) facc[0]=0.f;
    float m0=d_med[b*2+0], m1=d_med[b*2+1];
    float r0=1.f/fmaxf(d_scale[b*2+0],EPSf), r1=1.f/fmaxf(d_scale[b*2+1],EPSf);
    int fbase=(b*HWsz+blockIdx.x*CHUNK2)>>2;
    float acc=0.f;
    __syncthreads();
    #pragma unroll 4
    for(int j=0;j<CHUNK2/1024;j++){
        int f=fbase+j*256+t;
        unsigned mb=(d_mbits[f>>3]>>((f&7)*4))&0xFu;
        float4 vi=((const float4*)in)[f];
        float4 vt=((const float4*)tg)[f];
        float ei[4]={vi.x,vi.y,vi.z,vi.w};
        float et[4]={vt.x,vt.y,vt.z,vt.w};
        #pragma unroll
        for(int e=0;e<4;e++){
            if((mb>>e)&1u){
                float a=(ei[e]-m0)*r0, c=(et[e]-m1)*r1;
                acc+=fmaxf(fabsf(a-c),EPSf);
            }
        }
    }
    acc=wsumf(acc);
    if(lane==0) atomicAdd(&facc[0],acc);
    __syncthreads();
    if(t==0) atomicAdd(&d_gsum[b],facc[0]);
}

// ----------------------------- final (patch reduce + combine + cleanup) ------
__global__ __launch_bounds__(256) void k_final(float* out){
    __shared__ float r0[256];
    __shared__ float r1[256];
    int b=blockIdx.x, t=threadIdx.x;
    float s=0.f,c=0.f;
    for(int i=t;i<KTOP;i+=256) if(d_validp[b*KTOP+i]){ s+=d_ep[b*KTOP+i]; c+=1.f; }
    r0[t]=s; r1[t]=c; __syncthreads();
    #pragma unroll
    for(int st=128;st>0;st>>=1){ if(t<st){r0[t]+=r0[t+st]; r1[t]+=r1[t+st];} __syncthreads(); }
    if(t==0){
        float epatch=r0[0]/fmaxf(r1[0],1.f);
        float n=fmaxf((float)d_ncnt[b],1.f);
        float eg=sqrtf(fmaxf(d_gsum[b]/n,EPSf));
        out[b]=0.5f*(epatch+eg);
        d_ncnt[b]=0u; d_gsum[b]=0.f;                              // zero-on-consume
    }
}

// ----------------------------- launch ---------------------------------------
extern "C" void kernel_launch(void* const* d_in, const int* in_sizes, int n_in,
                              void* d_out, int out_size){
    const float* in =(const float*)d_in[0];
    const float* tg =(const float*)d_in[1];
    const void*  mk = d_in[2];
    const float* img=(const float*)d_in[3];
    const void*  vm = d_in[4];
    float* out=(float*)d_out;
    (void)in_sizes; (void)n_in; (void)out_size;

    k_packvm<<<BB*HWsz/4/256,256>>>(vm);
    k_hist_edge<<<HGRID+EGRID,256>>>(in,tg,mk,img);   // hist1 ∥ edge
    k_topk_sel<<<BB+BB*2,256>>>();                    // topk ∥ select1
    k_gather_patch<<<GGRID+PGRID,256>>>(in,tg);       // gather ∥ patch
    k_selectC<<<BB*2,256>>>();
    dim3 g2(NBG2,BB);
    k_gerr<<<g2,256>>>(in,tg);
    k_final<<<BB,256>>>(out);
}

// round 12
// speedup vs baseline: 1.4046x; 1.4046x over previous
#include <cuda_runtime.h>

// Problem constants (fixed shapes from setup_inputs)
#define BB 32
#define HH 480
#define WW 640
#define HWsz (HH*WW)          // 307200
#define CIM 3
#define OHh 34
#define OWw 45
#define NR 1530               // OHh*OWw
#define KTOP 153
#define RESH 14
#define PHLF 12
#define PSZ 625
#define EPSf 1e-5f
#define MIN_SAMP 4
#define NBG 30
#define CHUNK (HWsz/NBG)      // 10240
#define NBG2 60
#define CHUNK2 (HWsz/NBG2)    // 5120
#define RWORDS 20
#define IWORDS (HWsz/32)
#define PGRID (BB*KTOP)       // 4896 patches
#define PBLKS (PGRID/8)       // 612 patch blocks (8 warps = 8 patches each)
#define HGRID (NBG*BB)        // 960 hist blocks
#define EGRID (BB*NR*4/256)   // 765 edge blocks
#define GGRID (BB*NBG2)       // 1920 gather blocks
#define WSTRIDE 1506          // per-warp smem: 625 + 625 + 256 u32

// ----------------------------- scratch (zero-init; zero-on-consume) --------
__device__ unsigned d_mbits[BB*HWsz/32];
__device__ unsigned d_vbits[BB*HWsz/32];
__device__ float    d_resized[BB*NR];
__device__ int      d_coords[BB*KTOP*2];
__device__ float    d_ep[BB*KTOP];
__device__ int      d_validp[BB*KTOP];
__device__ unsigned d_hist1[BB*2*2048];       // zeroed by select1 after read
__device__ unsigned d_ncnt[BB];               // zeroed by k_final
__device__ unsigned d_sel1[BB*2];
__device__ unsigned d_cb1[BB*2];
__device__ float    d_med[BB*2];
__device__ float    d_scale[BB*2];
__device__ float    d_vsum[BB*2];             // zeroed by selectC
__device__ float    d_slo[BB*2];              // zeroed by selectC
__device__ float    d_gsum[BB];               // zeroed by k_final
__device__ unsigned d_ccnt[BB*2];             // zeroed by selectC
__device__ float    d_cand[(size_t)BB*2*HWsz];

// ----------------------------- helpers -------------------------------------
__device__ __forceinline__ unsigned keyf(float v){
    unsigned b=__float_as_uint(v);
    return b ^ ((b & 0x80000000u) ? 0xFFFFFFFFu : 0x80000000u);
}
__device__ __forceinline__ float unkey(unsigned k){
    unsigned b = (k & 0x80000000u) ? (k ^ 0x80000000u) : ~k;
    return __uint_as_float(b);
}
__device__ __forceinline__ float bsum256(float v, float* red, int t){
    red[t]=v; __syncthreads();
    #pragma unroll
    for(int s=128;s>0;s>>=1){ if(t<s) red[t]+=red[t+s]; __syncthreads(); }
    float r=red[0]; __syncthreads();
    return r;
}
__device__ __forceinline__ float wsumf(float v){
    #pragma unroll
    for(int o=16;o>0;o>>=1) v+=__shfl_xor_sync(0xffffffffu,v,o);
    return v;
}
__device__ __forceinline__ int detect_mode(const unsigned* m){
    unsigned lane=threadIdx.x&31;
    unsigned v0=m[lane], v1=m[lane+32];
    bool allb=__all_sync(0xffffffffu,(v0<=1u)&&(v1<=1u));
    bool allf=__all_sync(0xffffffffu,(v0==0u||v0==0x3F800000u)&&(v1==0u||v1==0x3F800000u));
    return allb?1:(allf?2:0);
}
// warp-aggregated histogram increment; only in uniform control flow.
__device__ __forceinline__ void aggInc(unsigned* h, unsigned bn){
    unsigned mm=__match_any_sync(0xffffffffu,bn);
    if(bn!=0xFFFFFFFFu){
        int leader=__ffs(mm)-1;
        if((int)(threadIdx.x&31)==leader) atomicAdd(&h[bn],(unsigned)__popc(mm));
    }
}

// single radix select (topk): rank kk ascending among valid keys (exact, 32-bit)
template<int NOWN>
__device__ __forceinline__ unsigned radix_sel(const unsigned (&key)[NOWN],
                                              const bool (&vl)[NOWN],
                                              unsigned kk,
                                              unsigned* hist, unsigned* wsum,
                                              unsigned* shb){
    int t=threadIdx.x, lane=t&31, wid=t>>5;
    unsigned prefix=0u;
    #pragma unroll
    for(int lvl=0;lvl<4;lvl++){
        const int sh=24-8*lvl;
        hist[t]=0u; __syncthreads();
        #pragma unroll
        for(int r=0;r<NOWN;r++){
            unsigned bn=0xFFFFFFFFu;
            if(vl[r]){
                unsigned k=key[r];
                bool ok=(lvl==0)||((k>>(sh+8))==prefix);
                if(ok) bn=(k>>sh)&255u;
            }
            aggInc(hist,bn);
        }
        __syncthreads();
        unsigned c=hist[t], x=c;
        #pragma unroll
        for(int o=1;o<32;o<<=1){ unsigned v=__shfl_up_sync(0xffffffffu,x,o); if(lane>=o)x+=v; }
        if(lane==31) wsum[wid]=x;
        __syncthreads();
        if(t==0){ unsigned s=0; for(int i=0;i<8;i++){ s+=wsum[i]; wsum[i]=s; } }
        __syncthreads();
        unsigned incl = x + (wid? wsum[wid-1]:0u);
        unsigned excl = incl - c;
        if(excl<=kk && kk<incl){ shb[0]=(unsigned)t; shb[1]=excl; }
        __syncthreads();
        prefix=(prefix<<8)|shb[0];
        kk-=shb[1];
        __syncthreads();
    }
    return prefix;
}

// ----------------------------- pack validity mask ----------------------------
__global__ __launch_bounds__(256) void k_packvm(const void* __restrict__ vm){
    int f=blockIdx.x*256+threadIdx.x;
    int mode=detect_mode((const unsigned*)vm);
    bool m0,m1,m2,m3;
    if(mode!=0){
        uint4 v=((const uint4*)vm)[f];
        m0=v.x!=0u; m1=v.y!=0u; m2=v.z!=0u; m3=v.w!=0u;
    } else {
        uchar4 v=((const uchar4*)vm)[f];
        m0=v.x; m1=v.y; m2=v.z; m3=v.w;
    }
    unsigned nib=(m0?1u:0u)|(m1?2u:0u)|(m2?4u:0u)|(m3?8u:0u);
    unsigned w=nib<<(4*(threadIdx.x&7));
    w|=__shfl_xor_sync(0xffffffffu,w,1);
    w|=__shfl_xor_sync(0xffffffffu,w,2);
    w|=__shfl_xor_sync(0xffffffffu,w,4);
    if((threadIdx.x&7)==0) d_vbits[f>>3]=w;
}

// ----------------------------- edge body -------------------------------------
__device__ __forceinline__ float edge_at(const float* __restrict__ img, int b, int y, int x){
    if(y<3 || y>HH-4 || x<3 || x>WW-4) return 0.f;
    int rb=b*IWORDS;
    int q=(x-1)>>5, s=(x-1)&31;
    unsigned a0=d_vbits[rb+(y-1)*RWORDS+q]&d_vbits[rb+y*RWORDS+q]&d_vbits[rb+(y+1)*RWORDS+q];
    unsigned bits;
    if(s<=29) bits=(a0>>s)&7u;
    else{
        unsigned a1=d_vbits[rb+(y-1)*RWORDS+q+1]&d_vbits[rb+y*RWORDS+q+1]&d_vbits[rb+(y+1)*RWORDS+q+1];
        bits=((a0>>s)|(a1<<(32-s)))&7u;
    }
    if(bits!=7u) return 0.f;
    float gx2=0.f, gy2=0.f;
    #pragma unroll
    for(int c=0;c<CIM;c++){
        const float* p = img + (size_t)(b*CIM+c)*HWsz;
        float v00=__ldg(&p[(y-1)*WW+x-1]), v01=__ldg(&p[(y-1)*WW+x]), v02=__ldg(&p[(y-1)*WW+x+1]);
        float v10=__ldg(&p[(y  )*WW+x-1]),                            v12=__ldg(&p[(y  )*WW+x+1]);
        float v20=__ldg(&p[(y+1)*WW+x-1]), v21=__ldg(&p[(y+1)*WW+x]), v22=__ldg(&p[(y+1)*WW+x+1]);
        float sx=((v02+2.f*v12+v22)-(v00+2.f*v10+v20))*0.125f;
        float sy=((v20+2.f*v21+v22)-(v00+2.f*v01+v02))*0.125f;
        gx2+=sx*sx; gy2+=sy*sy;
    }
    return sqrtf((gx2+gy2)*(1.f/3.f));
}

__device__ void edge_body(const float* __restrict__ img, int ebx){
    int gid=ebx*256+threadIdx.x;
    int id=gid>>2, corner=gid&3;
    int b=id/NR, o=id%NR, oy=o/OWw, ox=o%OWw;
    const float ry=(float)(480.0/34.0), rx=(float)(640.0/45.0);
    float cy=fminf(fmaxf((oy+0.5f)*ry-0.5f,0.f),(float)(HH-1));
    float cx=fminf(fmaxf((ox+0.5f)*rx-0.5f,0.f),(float)(WW-1));
    int y0=(int)floorf(cy), x0=(int)floorf(cx);
    int y1=min(y0+1,HH-1),  x1=min(x0+1,WW-1);
    float wy=cy-(float)y0,  wx=cx-(float)x0;
    int y=(corner&2)? y1:y0;
    int x=(corner&1)? x1:x0;
    float w=((corner&2)? wy:(1.f-wy))*((corner&1)? wx:(1.f-wx));
    float e=edge_at(img,b,y,x)*w;
    e+=__shfl_xor_sync(0xffffffffu,e,1);
    e+=__shfl_xor_sync(0xffffffffu,e,2);
    if(corner==0) d_resized[id]=e;
}

// ----------------------------- hist body (pack mk + level-1 histogram) -------
__device__ void hist_body(const float* __restrict__ in, const float* __restrict__ tg,
                          const void* __restrict__ mk, int b, int cx,
                          unsigned* h, float* red){
    int t=threadIdx.x;
    for(int i=t;i<4096;i+=256) h[i]=0u;
    int mode=detect_mode((const unsigned*)mk);
    __syncthreads();
    int fbase=(b*HWsz+cx*CHUNK)>>2;
    float sI=0.f,sT=0.f,nloc=0.f;
    #pragma unroll 2
    for(int j=0;j<CHUNK/1024;j++){
        int f=fbase+j*256+t;
        bool m[4];
        if(mode!=0){
            uint4 v=((const uint4*)mk)[f];
            m[0]=v.x!=0u; m[1]=v.y!=0u; m[2]=v.z!=0u; m[3]=v.w!=0u;
        } else {
            uchar4 v=((const uchar4*)mk)[f];
            m[0]=v.x; m[1]=v.y; m[2]=v.z; m[3]=v.w;
        }
        unsigned nib=(m[0]?1u:0u)|(m[1]?2u:0u)|(m[2]?4u:0u)|(m[3]?8u:0u);
        unsigned wv=nib<<(4*(t&7));
        wv|=__shfl_xor_sync(0xffffffffu,wv,1);
        wv|=__shfl_xor_sync(0xffffffffu,wv,2);
        wv|=__shfl_xor_sync(0xffffffffu,wv,4);
        if((t&7)==0) d_mbits[f>>3]=wv;
        float4 vi=((const float4*)in)[f];
        float4 vt=((const float4*)tg)[f];
        float ei[4]={vi.x,vi.y,vi.z,vi.w};
        float et[4]={vt.x,vt.y,vt.z,vt.w};
        #pragma unroll
        for(int e=0;e<4;e++){
            if(m[e]){
                atomicAdd(&h[keyf(ei[e])>>21],1u);
                atomicAdd(&h[2048u+(keyf(et[e])>>21)],1u);
                nloc+=1.f; sI+=ei[e]; sT+=et[e];
            }
        }
    }
    __syncthreads();
    for(int i=t;i<4096;i+=256){
        unsigned v=h[i];
        if(v) atomicAdd(&d_hist1[b*4096+i],v);
    }
    float rn=bsum256(nloc,red,t);
    float r0=bsum256(sI,red,t);
    float r1=bsum256(sT,red,t);
    if(t==0){
        atomicAdd(&d_ncnt[b],(unsigned)(rn+0.5f));
        atomicAdd(&d_vsum[b*2+0],r0);
        atomicAdd(&d_vsum[b*2+1],r1);
    }
}

__global__ __launch_bounds__(256) void k_hist_edge(const float* __restrict__ in,
                                                   const float* __restrict__ tg,
                                                   const void* __restrict__ mk,
                                                   const float* __restrict__ img){
    __shared__ unsigned h[4096];
    __shared__ float red[256];
    int bx=blockIdx.x;
    if(bx<HGRID) hist_body(in,tg,mk,bx%BB,bx/BB,h,red);
    else         edge_body(img,bx-HGRID);
}

// ----------------------------- merged top-k + level-1 select -----------------
__device__ void topk_body(unsigned* hist, unsigned* wsum, unsigned* shb,
                          int* ties, int* cnts){
    int b=blockIdx.x, t=threadIdx.x;
    unsigned key[6]; bool vl[6];
    #pragma unroll
    for(int r=0;r<6;r++){
        int i=t+256*r;
        vl[r]=(i<NR);
        key[r]= vl[r] ? keyf(d_resized[b*NR+i]) : 0u;
    }
    if(t==0){ cnts[0]=0; cnts[1]=0; }
    __syncthreads();
    unsigned T=radix_sel<6>(key,vl,(unsigned)(NR-KTOP),hist,wsum,shb);
    #pragma unroll
    for(int r=0;r<6;r++) if(vl[r]){
        int i=t+256*r;
        if(key[r]>T){
            int s=atomicAdd(&cnts[0],1);
            d_coords[(b*KTOP+s)*2+0]=(i/OWw)*RESH;
            d_coords[(b*KTOP+s)*2+1]=(i%OWw)*RESH;
        } else if(key[r]==T){
            int s=atomicAdd(&cnts[1],1);
            ties[s]=i;
        }
    }
    __syncthreads();
    int r_need=KTOP-cnts[0];
    int nt=cnts[1];
    for(int j=t;j<nt;j+=256){
        int idx=ties[j]; int rk=0;
        for(int q=0;q<nt;q++) rk+=(ties[q]<idx);
        if(rk<r_need){
            int s=cnts[0]+rk;
            d_coords[(b*KTOP+s)*2+0]=(idx/OWw)*RESH;
            d_coords[(b*KTOP+s)*2+1]=(idx%OWw)*RESH;
        }
    }
}
__device__ void select1_body(int bt, unsigned* stage, unsigned* part){
    int t=threadIdx.x;
    unsigned* gh=&d_hist1[(bt>>1)*4096+(bt&1)*2048];
    unsigned loc=0;
    #pragma unroll
    for(int i=0;i<8;i++){
        unsigned v=gh[t*8+i];
        gh[t*8+i]=0u;
        stage[t*8+i]=v;
        loc+=v;
    }
    part[t]=loc; __syncthreads();
    if(t!=0) return;
    unsigned n=d_ncnt[bt>>1];
    if(n==0){ d_sel1[bt]=0xFFFFFFFFu; d_cb1[bt]=0u; return; }
    unsigned kk=(n-1u)>>1;
    unsigned cum=0; int c=0;
    while(c<256 && cum+part[c]<=kk){ cum+=part[c]; c++; }
    int bin=c*8;
    while(cum+stage[bin]<=kk){ cum+=stage[bin]; bin++; }
    d_sel1[bt]=(unsigned)bin; d_cb1[bt]=cum;
}
__global__ __launch_bounds__(256) void k_topk_sel(){
    __shared__ unsigned sh[2304];
    __shared__ int cnts[2];
    if(blockIdx.x<BB)
        topk_body(sh,sh+256,sh+264,(int*)(sh+272),cnts);
    else
        select1_body(blockIdx.x-BB,sh,sh+2048);
}

// ----------------------------- gather body (block-staged compaction) ---------
__device__ void gather_body(const float* __restrict__ in, const float* __restrict__ tg,
                            int b, int cx, unsigned* sh, float* red){
    unsigned (*sbal0)[4]=(unsigned(*)[4])(sh);
    unsigned (*sbal1)[4]=(unsigned(*)[4])(sh+32);
    unsigned (*woff0)[4]=(unsigned(*)[4])(sh+64);
    unsigned (*woff1)[4]=(unsigned(*)[4])(sh+96);
    int t=threadIdx.x, lane=t&31, wid=t>>5;
    unsigned s0=d_sel1[b*2+0], s1=d_sel1[b*2+1];
    int fbase=(b*HWsz+cx*CHUNK2)>>2;
    float lo0=0.f, lo1=0.f;
    float* c0=&d_cand[(size_t)(b*2+0)*HWsz];
    float* c1=&d_cand[(size_t)(b*2+1)*HWsz];
    unsigned lmask=(1u<<lane)-1u;
    for(int j=0;j<CHUNK2/1024;j++){
        int f=fbase+j*256+t;
        unsigned mb=(d_mbits[f>>3]>>((f&7)*4))&0xFu;
        float4 vi=((const float4*)in)[f];
        float4 vt=((const float4*)tg)[f];
        float ei[4]={vi.x,vi.y,vi.z,vi.w};
        float et[4]={vt.x,vt.y,vt.z,vt.w};
        bool p0[4],p1[4];
        #pragma unroll
        for(int e=0;e<4;e++){
            bool a=(mb>>e)&1u;
            unsigned ki=a? keyf(ei[e]):0u;
            unsigned pi=ki>>21;
            p0[e]=a&&(pi==s0);
            if(a&&pi<s0) lo0+=ei[e];
            unsigned kt=a? keyf(et[e]):0u;
            unsigned pt=kt>>21;
            p1[e]=a&&(pt==s1);
            if(a&&pt<s1) lo1+=et[e];
        }
        #pragma unroll
        for(int e=0;e<4;e++){
            unsigned b0=__ballot_sync(0xffffffffu,p0[e]);
            unsigned b1=__ballot_sync(0xffffffffu,p1[e]);
            if(lane==0){ sbal0[wid][e]=b0; sbal1[wid][e]=b1; }
        }
        __syncthreads();
        if(t==0){
            unsigned run=0;
            #pragma unroll
            for(int w=0;w<8;w++)
                #pragma unroll
                for(int e=0;e<4;e++){ woff0[w][e]=run; run+=__popc(sbal0[w][e]); }
            unsigned base=run? atomicAdd(&d_ccnt[b*2+0],run):0u;
            #pragma unroll
            for(int w=0;w<8;w++)
                #pragma unroll
                for(int e=0;e<4;e++) woff0[w][e]+=base;
        } else if(t==32){
            unsigned run=0;
            #pragma unroll
            for(int w=0;w<8;w++)
                #pragma unroll
                for(int e=0;e<4;e++){ woff1[w][e]=run; run+=__popc(sbal1[w][e]); }
            unsigned base=run? atomicAdd(&d_ccnt[b*2+1],run):0u;
            #pragma unroll
            for(int w=0;w<8;w++)
                #pragma unroll
                for(int e=0;e<4;e++) woff1[w][e]+=base;
        }
        __syncthreads();
        #pragma unroll
        for(int e=0;e<4;e++){
            if(p0[e]) c0[woff0[wid][e]+__popc(sbal0[wid][e]&lmask)]=ei[e];
            if(p1[e]) c1[woff1[wid][e]+__popc(sbal1[wid][e]&lmask)]=et[e];
        }
        __syncthreads();
    }
    float r0=bsum256(lo0,red,t);
    float r1=bsum256(lo1,red,t);
    if(t==0){
        atomicAdd(&d_slo[b*2+0],r0);
        atomicAdd(&d_slo[b*2+1],r1);
    }
}

// ----------------------------- warp-level exact 4x8-bit radix select ---------
// keys: cnt compacted keys in per-warp smem; h: per-warp 256-bin histogram.
// Uniform control flow across the warp (cnt is warp-uniform). cnt>0 required.
__device__ unsigned warp_sel(const unsigned* keys, int cnt, unsigned kk, unsigned* h){
    int lane=threadIdx.x&31;
    const unsigned full=0xffffffffu;
    unsigned prefix=0u;
    int nslots=(cnt+31)>>5;
    #pragma unroll
    for(int lvl=0;lvl<4;lvl++){
        const int sh=24-8*lvl;
        #pragma unroll
        for(int i=0;i<8;i++) h[lane*8+i]=0u;
        __syncwarp();
        for(int r=0;r<nslots;r++){             // warp-uniform trip count
            int j=r*32+lane;
            unsigned bn=0xFFFFFFFFu;
            if(j<cnt){
                unsigned k=keys[j];
                if(lvl==0 || (k>>(sh+8))==prefix) bn=(k>>sh)&255u;
            }
            if(lvl==0) aggInc(h,bn);           // hot bins at top level
            else if(bn!=0xFFFFFFFFu) atomicAdd(&h[bn],1u);
        }
        __syncwarp();
        unsigned loc=0;
        #pragma unroll
        for(int i=0;i<8;i++) loc+=h[lane*8+i];
        unsigned x=loc;
        #pragma unroll
        for(int o=1;o<32;o<<=1){ unsigned v=__shfl_up_sync(full,x,o); if(lane>=o)x+=v; }
        unsigned excl=x-loc;
        bool win=(excl<=kk)&&(kk<x);
        unsigned wb=__ballot_sync(full,win);
        int wl=__ffs(wb)-1;                    // exactly one winner (kk<cnt)
        unsigned binsel=0u,newkk=0u;
        if(win){
            unsigned cum=excl; int i=0;
            while(cum+h[lane*8+i]<=kk){ cum+=h[lane*8+i]; i++; }
            binsel=(unsigned)(lane*8+i);
            newkk=kk-cum;
        }
        binsel=__shfl_sync(full,binsel,wl);
        kk=__shfl_sync(full,newkk,wl);
        prefix=(prefix<<8)|binsel;
        __syncwarp();
    }
    return prefix;
}

// ----------------------------- warp-per-patch SSI loss -----------------------
// No block barriers. ws: per-warp smem region of WSTRIDE u32:
//   [0,625) ka_s  [625,1250) kb_s  [1250,1506) hist
__device__ void patch_warp(const float* __restrict__ in, const float* __restrict__ tg,
                           int pat, unsigned* ws){
    int lane=threadIdx.x&31;
    const unsigned full=0xffffffffu;
    unsigned lmask=(1u<<lane)-1u;
    unsigned* ka_s=ws;
    unsigned* kb_s=ws+625;
    unsigned* h   =ws+1250;
    int b=pat/KTOP;
    int cy=d_coords[pat*2+0], cx=d_coords[pat*2+1];
    // load + compact (mask-aligned for both arrays)
    int cnt=0;
    #pragma unroll 4
    for(int r=0;r<20;r++){
        int i=r*32+lane;
        bool vl=false; float va=0.f, vb=0.f;
        if(i<PSZ){
            int y=cy+i/25-PHLF, x=cx+i%25-PHLF;
            if(y>=0&&y<HH&&x>=0&&x<WW){
                int gi=b*HWsz+y*WW+x;
                if((d_mbits[gi>>5]>>(gi&31))&1u){
                    vl=true; va=in[gi]; vb=tg[gi];
                }
            }
        }
        unsigned bal=__ballot_sync(full,vl);
        if(vl){
            int pos=cnt+__popc(bal&lmask);
            ka_s[pos]=keyf(va);
            kb_s[pos]=keyf(vb);
        }
        cnt+=__popc(bal);
    }
    __syncwarp();
    float medA=0.f, medB=0.f;
    if(cnt>0){
        unsigned kk=(unsigned)((cnt-1)>>1);
        medA=unkey(warp_sel(ka_s,cnt,kk,h));
        medB=unkey(warp_sel(kb_s,cnt,kk,h));
    }
    int nslots=(cnt+31)>>5;
    float s0=0.f,s1=0.f;
    for(int r=0;r<nslots;r++){
        int j=r*32+lane;
        if(j<cnt){
            s0+=fabsf(unkey(ka_s[j])-medA);
            s1+=fabsf(unkey(kb_s[j])-medB);
        }
    }
    s0=wsumf(s0); s1=wsumf(s1);
    float nf=fmaxf((float)cnt,1.f);
    float rA=1.f/fmaxf(s0/nf,EPSf), rB=1.f/fmaxf(s1/nf,EPSf);
    float es=0.f;
    for(int r=0;r<nslots;r++){
        int j=r*32+lane;
        if(j<cnt){
            float a=(unkey(ka_s[j])-medA)*rA, c=(unkey(kb_s[j])-medB)*rB;
            es+=fmaxf(fabsf(a-c),EPSf);
        }
    }
    es=wsumf(es);
    if(lane==0){
        d_ep[pat]=sqrtf(fmaxf(es/nf,EPSf));
        d_validp[pat]=(cnt>=MIN_SAMP);
    }
}

// merged launch: gather (BW-bound, 256-thr blocks) + patch (8 warps = 8 patches)
__global__ __launch_bounds__(256) void k_gather_patch(const float* __restrict__ in,
                                                      const float* __restrict__ tg){
    __shared__ unsigned shp[8*WSTRIDE];    // 48192 B
    int bx=blockIdx.x;
    if(bx<GGRID){
        gather_body(in,tg,bx%BB,bx/BB,shp,(float*)(shp+128));
    } else {
        int pb=bx-GGRID;                   // [0, PBLKS)
        int w=threadIdx.x>>5;
        patch_warp(in,tg,pb*8+w,shp+w*WSTRIDE);
    }
}

// ----------------------------- candidate select: exact median + scale --------
__global__ __launch_bounds__(256) void k_selectC(){
    __shared__ unsigned h[256];
    __shared__ unsigned wsum[8];
    __shared__ unsigned shb[2];
    __shared__ float rf[256];
    int bt=blockIdx.x; int b=bt>>1, t=threadIdx.x, lane=t&31, wid=t>>5;
    unsigned n=d_ncnt[b];
    unsigned sel1=d_sel1[bt];
    unsigned nc=d_ccnt[bt];
    unsigned cb1=d_cb1[bt];
    float vsum=0.f, slo0=0.f;
    if(t==0){ vsum=d_vsum[bt]; slo0=d_slo[bt]; }
    __syncthreads();
    if(t==0){ d_ccnt[bt]=0u; d_vsum[bt]=0.f; d_slo[bt]=0.f; }   // zero-on-consume
    if(n==0u || sel1==0xFFFFFFFFu){
        if(t==0){ d_med[bt]=0.f; d_scale[bt]=0.f; }
        return;
    }
    unsigned kk=((n-1u)>>1)-cb1;
    const float* cd=&d_cand[(size_t)bt*HWsz];
    unsigned pre=0u;
    const int SH[3]={13,5,0};
    const int BWD[3]={8,8,5};
    #pragma unroll
    for(int lvl=0;lvl<3;lvl++){
        int sh=SH[lvl];
        h[t]=0u; __syncthreads();
        for(unsigned i=t;i<nc;i+=256){
            unsigned k=keyf(cd[i])&0x1FFFFFu;
            if(lvl==0 || (k>>(sh+BWD[lvl]))==pre)
                atomicAdd(&h[(k>>sh)&((1u<<BWD[lvl])-1u)],1u);
        }
        __syncthreads();
        unsigned c=h[t], x=c;
        #pragma unroll
        for(int o=1;o<32;o<<=1){ unsigned v=__shfl_up_sync(0xffffffffu,x,o); if(lane>=o)x+=v; }
        if(lane==31) wsum[wid]=x;
        __syncthreads();
        if(t==0){ unsigned s=0; for(int i=0;i<8;i++){ s+=wsum[i]; wsum[i]=s; } }
        __syncthreads();
        unsigned incl=x+(wid?wsum[wid-1]:0u), excl=incl-c;
        if(excl<=kk && kk<incl){ shb[0]=(unsigned)t; shb[1]=excl; }
        __syncthreads();
        pre=(pre<<BWD[lvl])|shb[0];
        kk-=shb[1];
        __syncthreads();
    }
    unsigned medkey=(sel1<<21)|pre;
    float med=unkey(medkey);
    float sl=0.f, cl=0.f, ce=0.f;
    for(unsigned i=t;i<nc;i+=256){
        float v=cd[i];
        unsigned k=keyf(v);
        if(k<medkey){ sl+=v; cl+=1.f; }
        else if(k==medkey) ce+=1.f;
    }
    sl=bsum256(sl,rf,t);
    cl=bsum256(cl,rf,t);
    ce=bsum256(ce,rf,t);
    if(t==0){
        float C_lo=(float)cb1+cl;
        float S_lo=slo0+sl;
        float C_hi=(float)n-C_lo-ce;
        float S_hi=vsum-S_lo-ce*med;
        float sumabs=(S_hi-C_hi*med)+(C_lo*med-S_lo);
        d_med[bt]=med;
        d_scale[bt]=sumabs/fmaxf((float)n,1.f);
    }
}

// ----------------------------- global error pass -----------------------------
__global__ __launch_bounds__(256) void k_gerr(const float* __restrict__ in,
                                              const float* __restrict__ tg){
    __shared__ float red[256];
    int b=blockIdx.y, t=threadIdx.x;
    float m0=d_med[b*2+0], m1=d_med[b*2+1];
    float r0=1.f/fmaxf(d_scale[b*2+0],EPSf), r1=1.f/fmaxf(d_scale[b*2+1],EPSf);
    int fbase=(b*HWsz+blockIdx.x*CHUNK2)>>2;
    float acc=0.f;
    #pragma unroll 4
    for(int j=0;j<CHUNK2/1024;j++){
        int f=fbase+j*256+t;
        unsigned mb=(d_mbits[f>>3]>>((f&7)*4))&0xFu;
        float4 vi=((const float4*)in)[f];
        float4 vt=((const float4*)tg)[f];
        float ei[4]={vi.x,vi.y,vi.z,vi.w};
        float et[4]={vt.x,vt.y,vt.z,vt.w};
        #pragma unroll
        for(int e=0;e<4;e++){
            if((mb>>e)&1u){
                float a=(ei[e]-m0)*r0, c=(et[e]-m1)*r1;
                acc+=fmaxf(fabsf(a-c),EPSf);
            }
        }
    }
    float r=bsum256(acc,red,t);
    if(t==0) atomicAdd(&d_gsum[b],r);
}

// ----------------------------- final (patch reduce + combine + cleanup) ------
__global__ __launch_bounds__(256) void k_final(float* out){
    __shared__ float r0[256];
    __shared__ float r1[256];
    int b=blockIdx.x, t=threadIdx.x;
    float s=0.f,c=0.f;
    for(int i=t;i<KTOP;i+=256) if(d_validp[b*KTOP+i]){ s+=d_ep[b*KTOP+i]; c+=1.f; }
    r0[t]=s; r1[t]=c; __syncthreads();
    #pragma unroll
    for(int st=128;st>0;st>>=1){ if(t<st){r0[t]+=r0[t+st]; r1[t]+=r1[t+st];} __syncthreads(); }
    if(t==0){
        float epatch=r0[0]/fmaxf(r1[0],1.f);
        float n=fmaxf((float)d_ncnt[b],1.f);
        float eg=sqrtf(fmaxf(d_gsum[b]/n,EPSf));
        out[b]=0.5f*(epatch+eg);
        d_ncnt[b]=0u; d_gsum[b]=0.f;                              // zero-on-consume
    }
}

// ----------------------------- launch ---------------------------------------
extern "C" void kernel_launch(void* const* d_in, const int* in_sizes, int n_in,
                              void* d_out, int out_size){
    const float* in =(const float*)d_in[0];
    const float* tg =(const float*)d_in[1];
    const void*  mk = d_in[2];
    const float* img=(const float*)d_in[3];
    const void*  vm = d_in[4];
    float* out=(float*)d_out;
    (void)in_sizes; (void)n_in; (void)out_size;

    k_packvm<<<BB*HWsz/4/256,256>>>(vm);
    k_hist_edge<<<HGRID+EGRID,256>>>(in,tg,mk,img);   // hist1 ∥ edge
    k_topk_sel<<<BB+BB*2,256>>>();                    // topk ∥ select1
    k_gather_patch<<<GGRID+PBLKS,256>>>(in,tg);       // gather ∥ warp-per-patch
    k_selectC<<<BB*2,256>>>();
    dim3 g2(NBG2,BB);
    k_gerr<<<g2,256>>>(in,tg);
    k_final<<<BB,256>>>(out);
}